// round 12
// baseline (speedup 1.0000x reference)
#include <cuda_runtime.h>
#include <cuda_fp16.h>
#include <math.h>

#define NNODES 2048
#define NEDGES 32768
#define ECHUNK 8192

// ===========================================================================
// Compile-time e3nn real-basis Wigner 3j machinery
// ===========================================================================
__host__ __device__ constexpr double cfact(int n) {
    double r = 1.0;
    for (int i = 2; i <= n; i++) r *= (double)i;
    return r;
}
__host__ __device__ constexpr double csqrt(double x) {
    if (x <= 0.0) return 0.0;
    double g = x < 1.0 ? 1.0 : x;
    for (int i = 0; i < 80; i++) g = 0.5 * (g + x / g);
    return g;
}
struct CD { double re; double im; };
__host__ __device__ constexpr CD cmul(CD a, CD b) {
    return {a.re * b.re - a.im * b.im, a.re * b.im + a.im * b.re};
}

__host__ __device__ constexpr double su2cg(int j1, int m1, int j2, int m2, int j3, int m3) {
    if (m1 + m2 != m3) return 0.0;
    int vmin = -j1 + j2 + m3;
    if (-j1 + m1 > vmin) vmin = -j1 + m1;
    if (0 > vmin) vmin = 0;
    int vmax = j2 + j3 + m1;
    if (j3 - j1 + j2 < vmax) vmax = j3 - j1 + j2;
    if (j3 + m3 < vmax) vmax = j3 + m3;
    double c = csqrt((2.0 * j3 + 1.0) * cfact(j3 + j1 - j2) * cfact(j3 - j1 + j2) *
                     cfact(j1 + j2 - j3) / cfact(j1 + j2 + j3 + 1) *
                     cfact(j3 + m3) * cfact(j3 - m3) /
                     (cfact(j1 + m1) * cfact(j1 - m1) * cfact(j2 + m2) * cfact(j2 - m2)));
    double s = 0.0;
    for (int v = vmin; v <= vmax; v++) {
        double t = cfact(j2 + j3 + m1 - v) * cfact(j1 - m1 + v) /
                   (cfact(v) * cfact(j3 - j1 + j2 - v) * cfact(j3 + m3 - v) *
                    cfact(v + j1 - j2 - m3));
        s += ((v + j2 + m2) & 1) ? -t : t;
    }
    return c * s;
}

template <int L> struct QM { CD q[(2 * L + 1) * (2 * L + 1)]{}; };

template <int L> __host__ __device__ constexpr QM<L> buildq() {
    QM<L> Q{};
    constexpr int d = 2 * L + 1;
    const double r = csqrt(0.5);
    for (int m = -L; m < 0; m++) {
        Q.q[(L + m) * d + (L - m)] = {r, 0.0};
        Q.q[(L + m) * d + (L + m)] = {0.0, -r};
    }
    Q.q[L * d + L] = {1.0, 0.0};
    for (int m = 1; m <= L; m++) {
        double sg = (m & 1) ? -1.0 : 1.0;
        Q.q[(L + m) * d + (L + m)] = {sg * r, 0.0};
        Q.q[(L + m) * d + (L - m)] = {0.0, sg * r};
    }
    CD ph = (L % 4 == 0) ? CD{1.0, 0.0}
          : (L % 4 == 1) ? CD{0.0, -1.0}
          : (L % 4 == 2) ? CD{-1.0, 0.0}
                         : CD{0.0, 1.0};
    for (int i = 0; i < d * d; i++) Q.q[i] = cmul(Q.q[i], ph);
    return Q;
}

template <int L1, int L2, int L3> struct W3J {
    float c[(2 * L1 + 1) * (2 * L2 + 1) * (2 * L3 + 1)]{};
};

template <int L1, int L2, int L3> __host__ __device__ constexpr W3J<L1, L2, L3> w3j() {
    constexpr int d1 = 2 * L1 + 1, d2 = 2 * L2 + 1, d3 = 2 * L3 + 1;
    double C[d1 * d2 * d3]{};
    for (int m1 = -L1; m1 <= L1; m1++)
        for (int m2 = -L2; m2 <= L2; m2++) {
            int m3 = m1 + m2;
            if (m3 >= -L3 && m3 <= L3)
                C[((L1 + m1) * d2 + (L2 + m2)) * d3 + (L3 + m3)] = su2cg(L1, m1, L2, m2, L3, m3);
        }
    QM<L1> q1 = buildq<L1>();
    QM<L2> q2 = buildq<L2>();
    QM<L3> q3 = buildq<L3>();
    double out[d1 * d2 * d3]{};
    double ss = 0.0;
    for (int j = 0; j < d1; j++)
        for (int l = 0; l < d2; l++)
            for (int n = 0; n < d3; n++) {
                double re = 0.0;
                for (int i = 0; i < d1; i++)
                    for (int k = 0; k < d2; k++) {
                        CD ab = cmul(q1.q[i * d1 + j], q2.q[k * d2 + l]);
                        for (int m = 0; m < d3; m++) {
                            double cv = C[(i * d2 + k) * d3 + m];
                            if (cv != 0.0) {
                                CD g = q3.q[m * d3 + n];
                                re += cv * (ab.re * g.re + ab.im * g.im); // conj(g)
                            }
                        }
                    }
                out[(j * d2 + l) * d3 + n] = re;
                ss += re * re;
            }
    double inv = 1.0 / csqrt(ss);
    W3J<L1, L2, L3> R{};
    for (int idx = 0; idx < d1 * d2 * d3; idx++) R.c[idx] = (float)(out[idx] * inv);
    return R;
}

template <int L1, int L2, int L3> struct CGH {
    static constexpr W3J<L1, L2, L3> v = w3j<L1, L2, L3>();
};

__host__ __device__ constexpr bool rowAnyF(const float* c, int d2, int d3, int I, int J) {
    for (int k = 0; k < d3; k++)
        if (c[(I * d2 + J) * d3 + k] != 0.f) return true;
    return false;
}
template <int L1, int L2, int L3, int I, int J> struct RowAny {
    static constexpr bool value =
        rowAnyF(CGH<L1, L2, L3>::v.c, 2 * L2 + 1, 2 * L3 + 1, I, J);
};

template <int L1, int L2, int L3, int I, int J, int K>
__device__ __forceinline__ void tp_k(float t, float* dst) {
    if constexpr (K < 2 * L3 + 1) {
        constexpr float cv = CGH<L1, L2, L3>::v.c[(I * (2 * L2 + 1) + J) * (2 * L3 + 1) + K];
        if constexpr (cv != 0.f) dst[K] += t * cv;
        tp_k<L1, L2, L3, I, J, K + 1>(t, dst);
    }
}
template <int L1, int L2, int L3, int I, int J>
__device__ __forceinline__ void tp_ij(const float* wr, const float* vr, float* dst) {
    if constexpr (J < 2 * L2 + 1) {
        if constexpr (RowAny<L1, L2, L3, I, J>::value) {
            float t = wr[L1 * L1 + I] * vr[L2 * L2 + J];
            tp_k<L1, L2, L3, I, J, 0>(t, dst);
        }
        tp_ij<L1, L2, L3, I, J + 1>(wr, vr, dst);
    }
}
template <int L1, int L2, int L3, int I>
__device__ __forceinline__ void tp_i(const float* wr, const float* vr, float* dst) {
    if constexpr (I < 2 * L1 + 1) {
        tp_ij<L1, L2, L3, I, 0>(wr, vr, dst);
        tp_i<L1, L2, L3, I + 1>(wr, vr, dst);
    }
}
template <int L1, int L2, int L3>
__device__ __forceinline__ void tp_full(const float* wr, const float* vr, float* dst) {
#pragma unroll
    for (int k = 0; k < 2 * L3 + 1; k++) dst[k] = 0.f;
    tp_i<L1, L2, L3, 0>(wr, vr, dst);
}

__host__ __device__ constexpr double sh_scale(int which) {
    double n0 = 0.3, n1 = 0.5, n2 = 0.81;
    double inv = 1.0 / csqrt(n0 * n0 + n1 * n1 + n2 * n2);
    double ny[3] = {n1 * inv, n2 * inv, n0 * inv};
    constexpr W3J<1, 1, 2> cg112 = w3j<1, 1, 2>();
    constexpr W3J<2, 1, 3> cg213 = w3j<2, 1, 3>();
    double Y1[3] = {0, 0, 0};
    for (int i = 0; i < 3; i++) Y1[i] = csqrt(3.0) * ny[i];
    double A[5] = {0, 0, 0, 0, 0};
    for (int i = 0; i < 3; i++)
        for (int j = 0; j < 3; j++) {
            double t = Y1[i] * ny[j];
            for (int k = 0; k < 5; k++) A[k] += t * (double)cg112.c[(i * 3 + j) * 5 + k];
        }
    double na = 0;
    for (int k = 0; k < 5; k++) na += A[k] * A[k];
    double s0 = csqrt(5.0) / csqrt(na);
    if (which == 0) return s0;
    double Y2[5] = {0, 0, 0, 0, 0};
    for (int k = 0; k < 5; k++) Y2[k] = A[k] * s0;
    double B[7] = {0, 0, 0, 0, 0, 0, 0};
    for (int i = 0; i < 5; i++)
        for (int j = 0; j < 3; j++) {
            double t = Y2[i] * ny[j];
            for (int k = 0; k < 7; k++) B[k] += t * (double)cg213.c[(i * 3 + j) * 7 + k];
        }
    double nb = 0;
    for (int k = 0; k < 7; k++) nb += B[k] * B[k];
    return csqrt(7.0) / csqrt(nb);
}
constexpr float SH_S0 = (float)sh_scale(0);
constexpr float SH_S1 = (float)sh_scale(1);

// ===========================================================================
__device__ float g_silu_c;
__device__ __align__(16) float g_node_sum[NNODES * 1024];
__device__ __align__(16) float g_W0T[8192];
__device__ __align__(16) __half g_W1h[20480];   // [n=64][k=320]
__device__ __align__(16) __half g_Wg1h[20480];  // [u=64][mp=320]
__device__ __align__(16) __half g_Wg2h[20480];
__device__ __align__(16) __half g_vbufh[(size_t)8 * NEDGES * 320];
__device__ __align__(16) __half g_x2h[(size_t)NEDGES * 320];
__device__ __align__(16) float g_h1[(size_t)NEDGES * 64];

__device__ __forceinline__ void cp16(unsigned dst, const void* src) {
    asm volatile("cp.async.cg.shared.global [%0], [%1], 16;\n" :: "r"(dst), "l"(src));
}

// ---------------------------------------------------------------------------
__global__ void init_prep_kernel(const float* __restrict__ W0, const float* __restrict__ W1,
                                 const float* __restrict__ Wl1, const float* __restrict__ Wl2) {
    __shared__ float red[256];
    int tid = threadIdx.x, b = blockIdx.x;
    if (b == 0) {
        float part = 0.f;
        for (int i = tid; i < 20001; i += blockDim.x) {
            float z = -12.f + 24.f * (float)i / 20000.f;
            float s = z / (1.f + expf(-z));
            float phi = expf(-0.5f * z * z) * 0.3989422804014327f;
            float w = (i == 0 || i == 20000) ? 0.5f : 1.f;
            part += w * s * s * phi;
        }
        red[tid] = part;
        __syncthreads();
        for (int st = 128; st > 0; st >>= 1) {
            if (tid < st) red[tid] += red[tid + st];
            __syncthreads();
        }
        if (tid == 0) g_silu_c = rsqrtf(red[0] * (24.f / 20000.f));
    } else if (b < 273) {
        int i = (b - 1) * 256 + tid;
        if (i < 8192) {
            int k4 = i >> 8, rm = i & 255, u = rm >> 2, r = rm & 3;
            g_W0T[i] = W0[(k4 * 4 + r) * 64 + u];
            return;
        }
        i -= 8192;
        if (i < 20480) {
            int n = i / 320, k = i % 320;
            g_W1h[i] = __float2half_rn(W1[k * 64 + n]);
            return;
        }
        i -= 20480;
        if (i < 20480) {
            int u = i / 320, mp = i % 320, p = mp >> 6, um = mp & 63;
            g_Wg1h[i] = __float2half_rn(Wl1[(um * 5 + p) * 64 + u]);
            return;
        }
        i -= 20480;
        if (i < 20480) {
            int u = i / 320, mp = i % 320, p = mp >> 6, um = mp & 63;
            g_Wg2h[i] = __float2half_rn(Wl2[(um * 5 + p) * 64 + u]);
        }
    } else {
        int i = (b - 273) * 256 + tid;
        ((float4*)g_node_sum)[i] = make_float4(0.f, 0.f, 0.f, 0.f);
    }
}

// ---------------------------------------------------------------------------
// K1: w = x@W0/sqrt(128), SH, scatter, x->x2h
// ---------------------------------------------------------------------------
__global__ void __launch_bounds__(256) k1_scatter(const float* __restrict__ vectors,
                                                  const float* __restrict__ x,
                                                  const int* __restrict__ senders) {
    __shared__ __align__(16) float xs[16][128];
    __shared__ float ws[16][64];
    __shared__ float Ys[16][16];
    __shared__ int sends[16];
    int tid = threadIdx.x;
    int eb = blockIdx.x * 16;
    if (tid < 16) sends[tid] = senders[eb + tid];
#pragma unroll
    for (int r = 0; r < 2; r++) {
        int idx = tid + r * 256;
        int e = idx >> 5, q = idx & 31;
        float4 v = ((const float4*)(x + (size_t)(eb + e) * 128))[q];
        *(float4*)&xs[e][q * 4] = v;
        __half2 h0 = __floats2half2_rn(v.x, v.y);
        __half2 h1 = __floats2half2_rn(v.z, v.w);
        *(__half2*)(g_x2h + (size_t)(eb + e) * 320 + q * 4) = h0;
        *(__half2*)(g_x2h + (size_t)(eb + e) * 320 + q * 4 + 2) = h1;
    }
    __syncthreads();
    int g = tid >> 6, u = tid & 63;
    float acc[4] = {0, 0, 0, 0};
#pragma unroll
    for (int k4 = 0; k4 < 32; k4++) {
        float4 w = *(const float4*)&g_W0T[k4 * 256 + u * 4];
#pragma unroll
        for (int c = 0; c < 4; c++) {
            float4 xv = *(const float4*)&xs[g * 4 + c][k4 * 4];
            acc[c] += w.x * xv.x + w.y * xv.y + w.z * xv.z + w.w * xv.w;
        }
    }
#pragma unroll
    for (int c = 0; c < 4; c++) ws[g * 4 + c][u] = acc[c] * 0.08838834764831845f;
    if (tid < 16) {
        int e = eb + tid;
        float vx = vectors[3 * e], vy = vectors[3 * e + 1], vz = vectors[3 * e + 2];
        float inv = rsqrtf(vx * vx + vy * vy + vz * vz);
        float nb4[4] = {0.f, vy * inv, vz * inv, vx * inv};
        Ys[tid][0] = 1.f;
        float wb[4];
        wb[0] = 0.f;
#pragma unroll
        for (int i = 0; i < 3; i++) {
            wb[1 + i] = 1.7320508075688772f * nb4[1 + i];
            Ys[tid][1 + i] = wb[1 + i];
        }
        float Y2[5];
        tp_full<1, 1, 2>(wb, nb4, Y2);
        float wb2[9] = {0, 0, 0, 0, 0, 0, 0, 0, 0};
#pragma unroll
        for (int k = 0; k < 5; k++) {
            Y2[k] *= SH_S0;
            Ys[tid][4 + k] = Y2[k];
            wb2[4 + k] = Y2[k];
        }
        float Y3[7];
        tp_full<2, 1, 3>(wb2, nb4, Y3);
#pragma unroll
        for (int k = 0; k < 7; k++) Ys[tid][9 + k] = Y3[k] * SH_S1;
    }
    __syncthreads();
#pragma unroll
    for (int it = 0; it < 16; it++) {
        int t = tid + it * 256;
        int e = t >> 8, q = t & 255;
        int uu = q >> 2, i0 = (q & 3) * 4;
        float w = ws[e][uu];
        atomicAdd((float4*)(g_node_sum + (size_t)sends[e] * 1024 + q * 4),
                  make_float4(w * Ys[e][i0], w * Ys[e][i0 + 1], w * Ys[e][i0 + 2], w * Ys[e][i0 + 3]));
    }
}

// ---------------------------------------------------------------------------
// K2a: tensor product per edge (chunked), constexpr CG, fp16 outputs
// ---------------------------------------------------------------------------
__global__ void __launch_bounds__(256, 3) k2a_tp(const float* __restrict__ V,
                                                 const int* __restrict__ senders, int ebase) {
    __shared__ float wYs[4][64 * 17];
    __shared__ __align__(16) float Vs[4][576];
    __shared__ int sends[4];
    int tid = threadIdx.x;
    int eb = ebase + blockIdx.x * 4;
    if (tid < 4) sends[tid] = senders[eb + tid];
    __syncthreads();
    for (int t = tid; t < 1024; t += 256) {
        int sub = t >> 8, r = t & 255;
        float4 v = ((const float4*)(g_node_sum + (size_t)sends[sub] * 1024))[r];
        int uu = r >> 2, j0 = (r & 3) * 4;
        float* d = &wYs[sub][uu * 17 + j0];
        d[0] = v.x * 0.25f; d[1] = v.y * 0.25f; d[2] = v.z * 0.25f; d[3] = v.w * 0.25f;
    }
    for (int t = tid; t < 576; t += 256) {
        int sub = t / 144, r = t - sub * 144;
        ((float4*)Vs[sub])[r] = ((const float4*)(V + (size_t)(eb + sub) * 576))[r];
    }
    __syncthreads();
    int sub = tid >> 6, u = tid & 63;
    int e = eb + sub;
    float wr[16], vr[9];
#pragma unroll
    for (int j = 0; j < 16; j++) wr[j] = wYs[sub][u * 17 + j];
#pragma unroll
    for (int j = 0; j < 9; j++) vr[j] = Vs[sub][u * 9 + j];

    const float R3 = 1.7320508075688772f, R5 = 2.2360679774997896f;
    {
        float s0o[3], t1[1];
        tp_full<0, 0, 0>(wr, vr, t1); s0o[0] = t1[0];
        tp_full<1, 1, 0>(wr, vr, t1); s0o[1] = t1[0];
        tp_full<2, 2, 0>(wr, vr, t1); s0o[2] = t1[0];
        __half* x2p = g_x2h + (size_t)e * 320 + 128 + u * 3;
        x2p[0] = __float2half_rn(s0o[0]);
        x2p[1] = __float2half_rn(s0o[1]);
        x2p[2] = __float2half_rn(s0o[2]);
    }
    {
        float o1[5][3];
        tp_full<0, 1, 1>(wr, vr, o1[0]);
        tp_full<1, 0, 1>(wr, vr, o1[1]);
        tp_full<1, 2, 1>(wr, vr, o1[2]);
        tp_full<2, 1, 1>(wr, vr, o1[3]);
        tp_full<3, 2, 1>(wr, vr, o1[4]);
#pragma unroll
        for (int i = 0; i < 3; i++)
#pragma unroll
            for (int p = 0; p < 5; p++)
                g_vbufh[((size_t)i * NEDGES + e) * 320 + p * 64 + u] = __float2half_rn(R3 * o1[p][i]);
    }
    {
        float o2[5][5];
        tp_full<0, 2, 2>(wr, vr, o2[0]);
        tp_full<1, 1, 2>(wr, vr, o2[1]);
        tp_full<2, 0, 2>(wr, vr, o2[2]);
        tp_full<2, 2, 2>(wr, vr, o2[3]);
        tp_full<3, 1, 2>(wr, vr, o2[4]);
#pragma unroll
        for (int i = 0; i < 5; i++)
#pragma unroll
            for (int p = 0; p < 5; p++)
                g_vbufh[((size_t)(3 + i) * NEDGES + e) * 320 + p * 64 + u] = __float2half_rn(R5 * o2[p][i]);
    }
}

// ---------------------------------------------------------------------------
// K_gemm: fp16 m16n8k16, M-tile 128, 3-stage cp.async, 1 barrier/chunk
// ---------------------------------------------------------------------------
__global__ void __launch_bounds__(256, 4) k_gemm(float* __restrict__ Vout, int ebase) {
    __shared__ __align__(16) __half As[3][128 * 40];
    __shared__ __align__(16) __half Bs[3][64 * 40];
    int tid = threadIdx.x, s = blockIdx.y;
    int e0 = ebase + blockIdx.x * 128;
    const __half* Ab = (s < 8) ? g_vbufh + (size_t)s * NEDGES * 320 : g_x2h;
    const __half* Bm = (s < 3) ? g_Wg1h : (s < 8 ? g_Wg2h : g_W1h);
    int lane = tid & 31, warp = tid >> 5;
    int wm = warp & 3, wn = warp >> 2;
    int g = lane >> 2, tig = lane & 3;

    unsigned asA[3], asB[3];
#pragma unroll
    for (int st = 0; st < 3; st++) {
        asA[st] = (unsigned)__cvta_generic_to_shared(&As[st][0]);
        asB[st] = (unsigned)__cvta_generic_to_shared(&Bs[st][0]);
    }
    int arow = tid >> 2, ac8 = (tid & 3) * 8;
    int bn = tid >> 2;

    float acc[2][4][4];
#pragma unroll
    for (int a = 0; a < 2; a++)
#pragma unroll
        for (int b = 0; b < 4; b++)
#pragma unroll
            for (int c = 0; c < 4; c++) acc[a][b][c] = 0.f;

    // prologue: chunks 0 and 1
#pragma unroll
    for (int pc = 0; pc < 2; pc++) {
        int k0 = pc * 32;
        cp16(asA[pc] + (arow * 40 + ac8) * 2, Ab + (size_t)(e0 + arow) * 320 + k0 + ac8);
        cp16(asA[pc] + ((arow + 64) * 40 + ac8) * 2, Ab + (size_t)(e0 + arow + 64) * 320 + k0 + ac8);
        cp16(asB[pc] + (bn * 40 + ac8) * 2, Bm + (size_t)bn * 320 + k0 + ac8);
        asm volatile("cp.async.commit_group;\n");
    }

    for (int kc = 0; kc < 10; kc++) {
        int buf = kc - (kc / 3) * 3;
        if (kc == 9) asm volatile("cp.async.wait_group 0;\n");
        else asm volatile("cp.async.wait_group 1;\n");
        __syncthreads();
        if (kc + 2 < 10) {
            int nb = (kc + 2) - ((kc + 2) / 3) * 3;
            int k0 = (kc + 2) * 32;
            cp16(asA[nb] + (arow * 40 + ac8) * 2, Ab + (size_t)(e0 + arow) * 320 + k0 + ac8);
            cp16(asA[nb] + ((arow + 64) * 40 + ac8) * 2, Ab + (size_t)(e0 + arow + 64) * 320 + k0 + ac8);
            cp16(asB[nb] + (bn * 40 + ac8) * 2, Bm + (size_t)bn * 320 + k0 + ac8);
            asm volatile("cp.async.commit_group;\n");
        }
        const __half* Ac = As[buf];
        const __half* Bc = Bs[buf];
#pragma unroll
        for (int ks = 0; ks < 2; ks++) {
            int kb = ks * 16;
            unsigned af[2][4], bf[4][2];
#pragma unroll
            for (int tm = 0; tm < 2; tm++) {
                int r = wm * 32 + tm * 16 + g;
                af[tm][0] = *(const unsigned*)&Ac[r * 40 + kb + 2 * tig];
                af[tm][1] = *(const unsigned*)&Ac[(r + 8) * 40 + kb + 2 * tig];
                af[tm][2] = *(const unsigned*)&Ac[r * 40 + kb + 2 * tig + 8];
                af[tm][3] = *(const unsigned*)&Ac[(r + 8) * 40 + kb + 2 * tig + 8];
            }
#pragma unroll
            for (int tn = 0; tn < 4; tn++) {
                int c = wn * 32 + tn * 8 + g;
                bf[tn][0] = *(const unsigned*)&Bc[c * 40 + kb + 2 * tig];
                bf[tn][1] = *(const unsigned*)&Bc[c * 40 + kb + 2 * tig + 8];
            }
#pragma unroll
            for (int tm = 0; tm < 2; tm++)
#pragma unroll
                for (int tn = 0; tn < 4; tn++) {
                    asm volatile(
                        "mma.sync.aligned.m16n8k16.row.col.f32.f16.f16.f32 "
                        "{%0,%1,%2,%3}, {%4,%5,%6,%7}, {%8,%9}, {%0,%1,%2,%3};\n"
                        : "+f"(acc[tm][tn][0]), "+f"(acc[tm][tn][1]),
                          "+f"(acc[tm][tn][2]), "+f"(acc[tm][tn][3])
                        : "r"(af[tm][0]), "r"(af[tm][1]), "r"(af[tm][2]), "r"(af[tm][3]),
                          "r"(bf[tn][0]), "r"(bf[tn][1]));
                }
        }
    }

    const float scale = 0.05590169943749474f; // 1/sqrt(320)
    float silu_c = g_silu_c;
#pragma unroll
    for (int tm = 0; tm < 2; tm++)
#pragma unroll
        for (int tn = 0; tn < 4; tn++)
#pragma unroll
            for (int q = 0; q < 4; q++) {
                int r = wm * 32 + tm * 16 + g + ((q >= 2) ? 8 : 0);
                int u = wn * 32 + tn * 8 + 2 * tig + (q & 1);
                int e = e0 + r;
                float v = acc[tm][tn][q] * scale;
                if (s < 3) Vout[(size_t)e * 576 + 64 + u * 3 + s] = v;
                else if (s < 8) Vout[(size_t)e * 576 + 256 + u * 5 + (s - 3)] = v;
                else g_h1[(size_t)e * 64 + u] = silu_c * v / (1.f + __expf(-v));
            }
}

// ---------------------------------------------------------------------------
// K3: MLP layers 2+3, envelope, xout, zero Vout scalar block
// ---------------------------------------------------------------------------
__global__ void __launch_bounds__(256) k3_mlp(const float* __restrict__ vectors,
                                              const float* __restrict__ W2,
                                              const float* __restrict__ W3,
                                              float* __restrict__ xout,
                                              float* __restrict__ Vout) {
    __shared__ float h1s[4][64], h2s[4][64];
    int tid = threadIdx.x, sub = tid >> 6, u = tid & 63;
    int e = blockIdx.x * 4 + sub;
    h1s[sub][u] = g_h1[(size_t)e * 64 + u];
    float silu_c = g_silu_c;
    __syncthreads();
    float acc = 0.f;
#pragma unroll 8
    for (int k = 0; k < 64; k++) acc += h1s[sub][k] * W2[k * 64 + u];
    float z = acc * 0.125f;
    h2s[sub][u] = silu_c * z / (1.f + __expf(-z));
    __syncthreads();
    acc = 0.f;
#pragma unroll 8
    for (int k = 0; k < 64; k++) acc += h2s[sub][k] * W3[k * 64 + u];
    float vx = vectors[3 * e], vy = vectors[3 * e + 1], vz = vectors[3 * e + 2];
    float d = sqrtf(vx * vx + vy * vy + vz * vz);
    float d3 = d * d * d, d6 = d3 * d3;
    float env = (d < 1.f) ? 1.f + d6 * (-28.f + d * (48.f - 21.f * d)) : 0.f;
    xout[(size_t)e * 64 + u] = env * acc * 0.125f;
    Vout[(size_t)e * 576 + u] = 0.f;
}

// ---------------------------------------------------------------------------
extern "C" void kernel_launch(void* const* d_in, const int* in_sizes, int n_in,
                              void* d_out, int out_size) {
    const float* vectors = (const float*)d_in[0];
    const float* x       = (const float*)d_in[1];
    const float* V       = (const float*)d_in[2];
    const int*   senders = (const int*)d_in[3];
    const float* W0      = (const float*)d_in[4];
    const float* W1      = (const float*)d_in[5];
    const float* W2      = (const float*)d_in[6];
    const float* W3      = (const float*)d_in[7];
    const float* Wl1     = (const float*)d_in[8];
    const float* Wl2     = (const float*)d_in[9];
    float* xout = (float*)d_out;
    float* Vout = xout + (size_t)NEDGES * 64;

    init_prep_kernel<<<2321, 256>>>(W0, W1, Wl1, Wl2);
    k1_scatter<<<2048, 256>>>(vectors, x, senders);
    for (int c = 0; c < NEDGES / ECHUNK; c++) {
        k2a_tp<<<ECHUNK / 4, 256>>>(V, senders, c * ECHUNK);
        dim3 gg(ECHUNK / 128, 9);
        k_gemm<<<gg, 256>>>(Vout, c * ECHUNK);
    }
    k3_mlp<<<8192, 256>>>(vectors, W2, W3, xout, Vout);
}

// round 14
// speedup vs baseline: 1.0692x; 1.0692x over previous
#include <cuda_runtime.h>
#include <cuda_fp16.h>
#include <math.h>

#define NNODES 2048
#define NEDGES 32768

// ===========================================================================
// Compile-time e3nn real-basis Wigner 3j machinery
// ===========================================================================
__host__ __device__ constexpr double cfact(int n) {
    double r = 1.0;
    for (int i = 2; i <= n; i++) r *= (double)i;
    return r;
}
__host__ __device__ constexpr double csqrt(double x) {
    if (x <= 0.0) return 0.0;
    double g = x < 1.0 ? 1.0 : x;
    for (int i = 0; i < 80; i++) g = 0.5 * (g + x / g);
    return g;
}
struct CD { double re; double im; };
__host__ __device__ constexpr CD cmul(CD a, CD b) {
    return {a.re * b.re - a.im * b.im, a.re * b.im + a.im * b.re};
}

__host__ __device__ constexpr double su2cg(int j1, int m1, int j2, int m2, int j3, int m3) {
    if (m1 + m2 != m3) return 0.0;
    int vmin = -j1 + j2 + m3;
    if (-j1 + m1 > vmin) vmin = -j1 + m1;
    if (0 > vmin) vmin = 0;
    int vmax = j2 + j3 + m1;
    if (j3 - j1 + j2 < vmax) vmax = j3 - j1 + j2;
    if (j3 + m3 < vmax) vmax = j3 + m3;
    double c = csqrt((2.0 * j3 + 1.0) * cfact(j3 + j1 - j2) * cfact(j3 - j1 + j2) *
                     cfact(j1 + j2 - j3) / cfact(j1 + j2 + j3 + 1) *
                     cfact(j3 + m3) * cfact(j3 - m3) /
                     (cfact(j1 + m1) * cfact(j1 - m1) * cfact(j2 + m2) * cfact(j2 - m2)));
    double s = 0.0;
    for (int v = vmin; v <= vmax; v++) {
        double t = cfact(j2 + j3 + m1 - v) * cfact(j1 - m1 + v) /
                   (cfact(v) * cfact(j3 - j1 + j2 - v) * cfact(j3 + m3 - v) *
                    cfact(v + j1 - j2 - m3));
        s += ((v + j2 + m2) & 1) ? -t : t;
    }
    return c * s;
}

template <int L> struct QM { CD q[(2 * L + 1) * (2 * L + 1)]{}; };

template <int L> __host__ __device__ constexpr QM<L> buildq() {
    QM<L> Q{};
    constexpr int d = 2 * L + 1;
    const double r = csqrt(0.5);
    for (int m = -L; m < 0; m++) {
        Q.q[(L + m) * d + (L - m)] = {r, 0.0};
        Q.q[(L + m) * d + (L + m)] = {0.0, -r};
    }
    Q.q[L * d + L] = {1.0, 0.0};
    for (int m = 1; m <= L; m++) {
        double sg = (m & 1) ? -1.0 : 1.0;
        Q.q[(L + m) * d + (L + m)] = {sg * r, 0.0};
        Q.q[(L + m) * d + (L - m)] = {0.0, sg * r};
    }
    CD ph = (L % 4 == 0) ? CD{1.0, 0.0}
          : (L % 4 == 1) ? CD{0.0, -1.0}
          : (L % 4 == 2) ? CD{-1.0, 0.0}
                         : CD{0.0, 1.0};
    for (int i = 0; i < d * d; i++) Q.q[i] = cmul(Q.q[i], ph);
    return Q;
}

template <int L1, int L2, int L3> struct W3J {
    float c[(2 * L1 + 1) * (2 * L2 + 1) * (2 * L3 + 1)]{};
};

template <int L1, int L2, int L3> __host__ __device__ constexpr W3J<L1, L2, L3> w3j() {
    constexpr int d1 = 2 * L1 + 1, d2 = 2 * L2 + 1, d3 = 2 * L3 + 1;
    double C[d1 * d2 * d3]{};
    for (int m1 = -L1; m1 <= L1; m1++)
        for (int m2 = -L2; m2 <= L2; m2++) {
            int m3 = m1 + m2;
            if (m3 >= -L3 && m3 <= L3)
                C[((L1 + m1) * d2 + (L2 + m2)) * d3 + (L3 + m3)] = su2cg(L1, m1, L2, m2, L3, m3);
        }
    QM<L1> q1 = buildq<L1>();
    QM<L2> q2 = buildq<L2>();
    QM<L3> q3 = buildq<L3>();
    double out[d1 * d2 * d3]{};
    double ss = 0.0;
    for (int j = 0; j < d1; j++)
        for (int l = 0; l < d2; l++)
            for (int n = 0; n < d3; n++) {
                double re = 0.0;
                for (int i = 0; i < d1; i++)
                    for (int k = 0; k < d2; k++) {
                        CD ab = cmul(q1.q[i * d1 + j], q2.q[k * d2 + l]);
                        for (int m = 0; m < d3; m++) {
                            double cv = C[(i * d2 + k) * d3 + m];
                            if (cv != 0.0) {
                                CD g = q3.q[m * d3 + n];
                                re += cv * (ab.re * g.re + ab.im * g.im); // conj(g)
                            }
                        }
                    }
                out[(j * d2 + l) * d3 + n] = re;
                ss += re * re;
            }
    double inv = 1.0 / csqrt(ss);
    W3J<L1, L2, L3> R{};
    for (int idx = 0; idx < d1 * d2 * d3; idx++) R.c[idx] = (float)(out[idx] * inv);
    return R;
}

template <int L1, int L2, int L3> struct CGH {
    static constexpr W3J<L1, L2, L3> v = w3j<L1, L2, L3>();
};

__host__ __device__ constexpr bool rowAnyF(const float* c, int d2, int d3, int I, int J) {
    for (int k = 0; k < d3; k++)
        if (c[(I * d2 + J) * d3 + k] != 0.f) return true;
    return false;
}
template <int L1, int L2, int L3, int I, int J> struct RowAny {
    static constexpr bool value =
        rowAnyF(CGH<L1, L2, L3>::v.c, 2 * L2 + 1, 2 * L3 + 1, I, J);
};

template <int L1, int L2, int L3, int I, int J, int K>
__device__ __forceinline__ void tp_k(float t, float* dst) {
    if constexpr (K < 2 * L3 + 1) {
        constexpr float cv = CGH<L1, L2, L3>::v.c[(I * (2 * L2 + 1) + J) * (2 * L3 + 1) + K];
        if constexpr (cv != 0.f) dst[K] += t * cv;
        tp_k<L1, L2, L3, I, J, K + 1>(t, dst);
    }
}
template <int L1, int L2, int L3, int I, int J>
__device__ __forceinline__ void tp_ij(const float* wr, const float* vr, float* dst) {
    if constexpr (J < 2 * L2 + 1) {
        if constexpr (RowAny<L1, L2, L3, I, J>::value) {
            float t = wr[L1 * L1 + I] * vr[L2 * L2 + J];
            tp_k<L1, L2, L3, I, J, 0>(t, dst);
        }
        tp_ij<L1, L2, L3, I, J + 1>(wr, vr, dst);
    }
}
template <int L1, int L2, int L3, int I>
__device__ __forceinline__ void tp_i(const float* wr, const float* vr, float* dst) {
    if constexpr (I < 2 * L1 + 1) {
        tp_ij<L1, L2, L3, I, 0>(wr, vr, dst);
        tp_i<L1, L2, L3, I + 1>(wr, vr, dst);
    }
}
template <int L1, int L2, int L3>
__device__ __forceinline__ void tp_full(const float* wr, const float* vr, float* dst) {
#pragma unroll
    for (int k = 0; k < 2 * L3 + 1; k++) dst[k] = 0.f;
    tp_i<L1, L2, L3, 0>(wr, vr, dst);
}

__host__ __device__ constexpr double sh_scale(int which) {
    double n0 = 0.3, n1 = 0.5, n2 = 0.81;
    double inv = 1.0 / csqrt(n0 * n0 + n1 * n1 + n2 * n2);
    double ny[3] = {n1 * inv, n2 * inv, n0 * inv};
    constexpr W3J<1, 1, 2> cg112 = w3j<1, 1, 2>();
    constexpr W3J<2, 1, 3> cg213 = w3j<2, 1, 3>();
    double Y1[3] = {0, 0, 0};
    for (int i = 0; i < 3; i++) Y1[i] = csqrt(3.0) * ny[i];
    double A[5] = {0, 0, 0, 0, 0};
    for (int i = 0; i < 3; i++)
        for (int j = 0; j < 3; j++) {
            double t = Y1[i] * ny[j];
            for (int k = 0; k < 5; k++) A[k] += t * (double)cg112.c[(i * 3 + j) * 5 + k];
        }
    double na = 0;
    for (int k = 0; k < 5; k++) na += A[k] * A[k];
    double s0 = csqrt(5.0) / csqrt(na);
    if (which == 0) return s0;
    double Y2[5] = {0, 0, 0, 0, 0};
    for (int k = 0; k < 5; k++) Y2[k] = A[k] * s0;
    double B[7] = {0, 0, 0, 0, 0, 0, 0};
    for (int i = 0; i < 5; i++)
        for (int j = 0; j < 3; j++) {
            double t = Y2[i] * ny[j];
            for (int k = 0; k < 7; k++) B[k] += t * (double)cg213.c[(i * 3 + j) * 7 + k];
        }
    double nb = 0;
    for (int k = 0; k < 7; k++) nb += B[k] * B[k];
    return csqrt(7.0) / csqrt(nb);
}
constexpr float SH_S0 = (float)sh_scale(0);
constexpr float SH_S1 = (float)sh_scale(1);

// ===========================================================================
__device__ float g_silu_c;
__device__ __align__(16) float g_node_sum[NNODES * 1024];
__device__ __align__(16) float g_W0T[8192];
__device__ __align__(16) __half g_W1h[20480];   // [n=64][k=320]
__device__ __align__(16) __half g_Wg1h[20480];  // [u=64][mp=320]
__device__ __align__(16) __half g_Wg2h[20480];
__device__ __align__(16) __half g_vbufh[(size_t)8 * NEDGES * 320];
__device__ __align__(16) __half g_x2h[(size_t)NEDGES * 320];
__device__ __align__(16) float g_h1[(size_t)NEDGES * 64];

__device__ __forceinline__ void cp16(unsigned dst, const void* src) {
    asm volatile("cp.async.cg.shared.global [%0], [%1], 16;\n" :: "r"(dst), "l"(src));
}

// ---------------------------------------------------------------------------
// init: block 0 = silu_c; [1,273) = weight prep; [273,2321) = zero node_sum
// ---------------------------------------------------------------------------
__global__ void init_prep_kernel(const float* __restrict__ W0, const float* __restrict__ W1,
                                 const float* __restrict__ Wl1, const float* __restrict__ Wl2) {
    __shared__ float red[256];
    int tid = threadIdx.x, b = blockIdx.x;
    if (b == 0) {
        float part = 0.f;
        for (int i = tid; i < 20001; i += blockDim.x) {
            float z = -12.f + 24.f * (float)i / 20000.f;
            float s = z / (1.f + expf(-z));
            float phi = expf(-0.5f * z * z) * 0.3989422804014327f;
            float w = (i == 0 || i == 20000) ? 0.5f : 1.f;
            part += w * s * s * phi;
        }
        red[tid] = part;
        __syncthreads();
        for (int st = 128; st > 0; st >>= 1) {
            if (tid < st) red[tid] += red[tid + st];
            __syncthreads();
        }
        if (tid == 0) g_silu_c = rsqrtf(red[0] * (24.f / 20000.f));
    } else if (b < 273) {
        int i = (b - 1) * 256 + tid;
        if (i < 8192) {
            int k4 = i >> 8, rm = i & 255, u = rm >> 2, r = rm & 3;
            g_W0T[i] = W0[(k4 * 4 + r) * 64 + u];
            return;
        }
        i -= 8192;
        if (i < 20480) {
            int n = i / 320, k = i % 320;
            g_W1h[i] = __float2half_rn(W1[k * 64 + n]);
            return;
        }
        i -= 20480;
        if (i < 20480) {
            int u = i / 320, mp = i % 320, p = mp >> 6, um = mp & 63;
            g_Wg1h[i] = __float2half_rn(Wl1[(um * 5 + p) * 64 + u]);
            return;
        }
        i -= 20480;
        if (i < 20480) {
            int u = i / 320, mp = i % 320, p = mp >> 6, um = mp & 63;
            g_Wg2h[i] = __float2half_rn(Wl2[(um * 5 + p) * 64 + u]);
        }
    } else {
        int i = (b - 273) * 256 + tid;
        ((float4*)g_node_sum)[i] = make_float4(0.f, 0.f, 0.f, 0.f);
    }
}

// ---------------------------------------------------------------------------
// K1: w = x@W0/sqrt(128), SH, scatter, x->x2h
// ---------------------------------------------------------------------------
__global__ void __launch_bounds__(256) k1_scatter(const float* __restrict__ vectors,
                                                  const float* __restrict__ x,
                                                  const int* __restrict__ senders) {
    __shared__ __align__(16) float xs[16][128];
    __shared__ float ws[16][64];
    __shared__ float Ys[16][16];
    __shared__ int sends[16];
    int tid = threadIdx.x;
    int eb = blockIdx.x * 16;
    if (tid < 16) sends[tid] = senders[eb + tid];
#pragma unroll
    for (int r = 0; r < 2; r++) {
        int idx = tid + r * 256;
        int e = idx >> 5, q = idx & 31;
        float4 v = ((const float4*)(x + (size_t)(eb + e) * 128))[q];
        *(float4*)&xs[e][q * 4] = v;
        __half2 h0 = __floats2half2_rn(v.x, v.y);
        __half2 h1 = __floats2half2_rn(v.z, v.w);
        *(__half2*)(g_x2h + (size_t)(eb + e) * 320 + q * 4) = h0;
        *(__half2*)(g_x2h + (size_t)(eb + e) * 320 + q * 4 + 2) = h1;
    }
    __syncthreads();
    int g = tid >> 6, u = tid & 63;
    float acc[4] = {0, 0, 0, 0};
#pragma unroll
    for (int k4 = 0; k4 < 32; k4++) {
        float4 w = *(const float4*)&g_W0T[k4 * 256 + u * 4];
#pragma unroll
        for (int c = 0; c < 4; c++) {
            float4 xv = *(const float4*)&xs[g * 4 + c][k4 * 4];
            acc[c] += w.x * xv.x + w.y * xv.y + w.z * xv.z + w.w * xv.w;
        }
    }
#pragma unroll
    for (int c = 0; c < 4; c++) ws[g * 4 + c][u] = acc[c] * 0.08838834764831845f;
    if (tid < 16) {
        int e = eb + tid;
        float vx = vectors[3 * e], vy = vectors[3 * e + 1], vz = vectors[3 * e + 2];
        float inv = rsqrtf(vx * vx + vy * vy + vz * vz);
        float nb4[4] = {0.f, vy * inv, vz * inv, vx * inv};
        Ys[tid][0] = 1.f;
        float wb[4];
        wb[0] = 0.f;
#pragma unroll
        for (int i = 0; i < 3; i++) {
            wb[1 + i] = 1.7320508075688772f * nb4[1 + i];
            Ys[tid][1 + i] = wb[1 + i];
        }
        float Y2[5];
        tp_full<1, 1, 2>(wb, nb4, Y2);
        float wb2[9] = {0, 0, 0, 0, 0, 0, 0, 0, 0};
#pragma unroll
        for (int k = 0; k < 5; k++) {
            Y2[k] *= SH_S0;
            Ys[tid][4 + k] = Y2[k];
            wb2[4 + k] = Y2[k];
        }
        float Y3[7];
        tp_full<2, 1, 3>(wb2, nb4, Y3);
#pragma unroll
        for (int k = 0; k < 7; k++) Ys[tid][9 + k] = Y3[k] * SH_S1;
    }
    __syncthreads();
#pragma unroll
    for (int it = 0; it < 16; it++) {
        int t = tid + it * 256;
        int e = t >> 8, q = t & 255;
        int uu = q >> 2, i0 = (q & 3) * 4;
        float w = ws[e][uu];
        atomicAdd((float4*)(g_node_sum + (size_t)sends[e] * 1024 + q * 4),
                  make_float4(w * Ys[e][i0], w * Ys[e][i0 + 1], w * Ys[e][i0 + 2], w * Ys[e][i0 + 3]));
    }
}

// ---------------------------------------------------------------------------
// K2a: tensor product per edge, constexpr CG, fp16 outputs
// ---------------------------------------------------------------------------
__global__ void __launch_bounds__(256, 3) k2a_tp(const float* __restrict__ V,
                                                 const int* __restrict__ senders) {
    __shared__ float wYs[4][64 * 17];
    __shared__ __align__(16) float Vs[4][576];
    __shared__ int sends[4];
    int tid = threadIdx.x;
    int eb = blockIdx.x * 4;
    if (tid < 4) sends[tid] = senders[eb + tid];
    __syncthreads();
    for (int t = tid; t < 1024; t += 256) {
        int sub = t >> 8, r = t & 255;
        float4 v = ((const float4*)(g_node_sum + (size_t)sends[sub] * 1024))[r];
        int uu = r >> 2, j0 = (r & 3) * 4;
        float* d = &wYs[sub][uu * 17 + j0];
        d[0] = v.x * 0.25f; d[1] = v.y * 0.25f; d[2] = v.z * 0.25f; d[3] = v.w * 0.25f;
    }
    for (int t = tid; t < 576; t += 256) {
        int sub = t / 144, r = t - sub * 144;
        ((float4*)Vs[sub])[r] = ((const float4*)(V + (size_t)(eb + sub) * 576))[r];
    }
    __syncthreads();
    int sub = tid >> 6, u = tid & 63;
    int e = eb + sub;
    float wr[16], vr[9];
#pragma unroll
    for (int j = 0; j < 16; j++) wr[j] = wYs[sub][u * 17 + j];
#pragma unroll
    for (int j = 0; j < 9; j++) vr[j] = Vs[sub][u * 9 + j];

    const float R3 = 1.7320508075688772f, R5 = 2.2360679774997896f;
    {
        float s0o[3], t1[1];
        tp_full<0, 0, 0>(wr, vr, t1); s0o[0] = t1[0];
        tp_full<1, 1, 0>(wr, vr, t1); s0o[1] = t1[0];
        tp_full<2, 2, 0>(wr, vr, t1); s0o[2] = t1[0];
        __half* x2p = g_x2h + (size_t)e * 320 + 128 + u * 3;
        x2p[0] = __float2half_rn(s0o[0]);
        x2p[1] = __float2half_rn(s0o[1]);
        x2p[2] = __float2half_rn(s0o[2]);
    }
    {
        float o1[5][3];
        tp_full<0, 1, 1>(wr, vr, o1[0]);
        tp_full<1, 0, 1>(wr, vr, o1[1]);
        tp_full<1, 2, 1>(wr, vr, o1[2]);
        tp_full<2, 1, 1>(wr, vr, o1[3]);
        tp_full<3, 2, 1>(wr, vr, o1[4]);
#pragma unroll
        for (int i = 0; i < 3; i++)
#pragma unroll
            for (int p = 0; p < 5; p++)
                g_vbufh[((size_t)i * NEDGES + e) * 320 + p * 64 + u] = __float2half_rn(R3 * o1[p][i]);
    }
    {
        float o2[5][5];
        tp_full<0, 2, 2>(wr, vr, o2[0]);
        tp_full<1, 1, 2>(wr, vr, o2[1]);
        tp_full<2, 0, 2>(wr, vr, o2[2]);
        tp_full<2, 2, 2>(wr, vr, o2[3]);
        tp_full<3, 1, 2>(wr, vr, o2[4]);
#pragma unroll
        for (int i = 0; i < 5; i++)
#pragma unroll
            for (int p = 0; p < 5; p++)
                g_vbufh[((size_t)(3 + i) * NEDGES + e) * 320 + p * 64 + u] = __float2half_rn(R5 * o2[p][i]);
    }
}

// ---------------------------------------------------------------------------
// K_gemm: fp16 m16n8k16, M-tile 128, 3-stage cp.async, 1 barrier/chunk
// ---------------------------------------------------------------------------
__global__ void __launch_bounds__(256, 4) k_gemm(float* __restrict__ Vout) {
    __shared__ __align__(16) __half As[3][128 * 40];
    __shared__ __align__(16) __half Bs[3][64 * 40];
    int tid = threadIdx.x, s = blockIdx.y;
    int e0 = blockIdx.x * 128;
    const __half* Ab = (s < 8) ? g_vbufh + (size_t)s * NEDGES * 320 : g_x2h;
    const __half* Bm = (s < 3) ? g_Wg1h : (s < 8 ? g_Wg2h : g_W1h);
    int lane = tid & 31, warp = tid >> 5;
    int wm = warp & 3, wn = warp >> 2;
    int g = lane >> 2, tig = lane & 3;

    unsigned asA[3], asB[3];
#pragma unroll
    for (int st = 0; st < 3; st++) {
        asA[st] = (unsigned)__cvta_generic_to_shared(&As[st][0]);
        asB[st] = (unsigned)__cvta_generic_to_shared(&Bs[st][0]);
    }
    int arow = tid >> 2, ac8 = (tid & 3) * 8;
    int bn = tid >> 2;

    float acc[2][4][4];
#pragma unroll
    for (int a = 0; a < 2; a++)
#pragma unroll
        for (int b = 0; b < 4; b++)
#pragma unroll
            for (int c = 0; c < 4; c++) acc[a][b][c] = 0.f;

    // prologue: chunks 0 and 1
#pragma unroll
    for (int pc = 0; pc < 2; pc++) {
        int k0 = pc * 32;
        cp16(asA[pc] + (arow * 40 + ac8) * 2, Ab + (size_t)(e0 + arow) * 320 + k0 + ac8);
        cp16(asA[pc] + ((arow + 64) * 40 + ac8) * 2, Ab + (size_t)(e0 + arow + 64) * 320 + k0 + ac8);
        cp16(asB[pc] + (bn * 40 + ac8) * 2, Bm + (size_t)bn * 320 + k0 + ac8);
        asm volatile("cp.async.commit_group;\n");
    }

    for (int kc = 0; kc < 10; kc++) {
        int buf = kc - (kc / 3) * 3;
        if (kc == 9) asm volatile("cp.async.wait_group 0;\n");
        else asm volatile("cp.async.wait_group 1;\n");
        __syncthreads();
        if (kc + 2 < 10) {
            int nb = (kc + 2) - ((kc + 2) / 3) * 3;
            int k0 = (kc + 2) * 32;
            cp16(asA[nb] + (arow * 40 + ac8) * 2, Ab + (size_t)(e0 + arow) * 320 + k0 + ac8);
            cp16(asA[nb] + ((arow + 64) * 40 + ac8) * 2, Ab + (size_t)(e0 + arow + 64) * 320 + k0 + ac8);
            cp16(asB[nb] + (bn * 40 + ac8) * 2, Bm + (size_t)bn * 320 + k0 + ac8);
            asm volatile("cp.async.commit_group;\n");
        }
        const __half* Ac = As[buf];
        const __half* Bc = Bs[buf];
#pragma unroll
        for (int ks = 0; ks < 2; ks++) {
            int kb = ks * 16;
            unsigned af[2][4], bf[4][2];
#pragma unroll
            for (int tm = 0; tm < 2; tm++) {
                int r = wm * 32 + tm * 16 + g;
                af[tm][0] = *(const unsigned*)&Ac[r * 40 + kb + 2 * tig];
                af[tm][1] = *(const unsigned*)&Ac[(r + 8) * 40 + kb + 2 * tig];
                af[tm][2] = *(const unsigned*)&Ac[r * 40 + kb + 2 * tig + 8];
                af[tm][3] = *(const unsigned*)&Ac[(r + 8) * 40 + kb + 2 * tig + 8];
            }
#pragma unroll
            for (int tn = 0; tn < 4; tn++) {
                int c = wn * 32 + tn * 8 + g;
                bf[tn][0] = *(const unsigned*)&Bc[c * 40 + kb + 2 * tig];
                bf[tn][1] = *(const unsigned*)&Bc[c * 40 + kb + 2 * tig + 8];
            }
#pragma unroll
            for (int tm = 0; tm < 2; tm++)
#pragma unroll
                for (int tn = 0; tn < 4; tn++) {
                    asm volatile(
                        "mma.sync.aligned.m16n8k16.row.col.f32.f16.f16.f32 "
                        "{%0,%1,%2,%3}, {%4,%5,%6,%7}, {%8,%9}, {%0,%1,%2,%3};\n"
                        : "+f"(acc[tm][tn][0]), "+f"(acc[tm][tn][1]),
                          "+f"(acc[tm][tn][2]), "+f"(acc[tm][tn][3])
                        : "r"(af[tm][0]), "r"(af[tm][1]), "r"(af[tm][2]), "r"(af[tm][3]),
                          "r"(bf[tn][0]), "r"(bf[tn][1]));
                }
        }
    }

    const float scale = 0.05590169943749474f; // 1/sqrt(320)
    float silu_c = g_silu_c;
#pragma unroll
    for (int tm = 0; tm < 2; tm++)
#pragma unroll
        for (int tn = 0; tn < 4; tn++)
#pragma unroll
            for (int q = 0; q < 4; q++) {
                int r = wm * 32 + tm * 16 + g + ((q >= 2) ? 8 : 0);
                int u = wn * 32 + tn * 8 + 2 * tig + (q & 1);
                int e = e0 + r;
                float v = acc[tm][tn][q] * scale;
                if (s < 3) Vout[(size_t)e * 576 + 64 + u * 3 + s] = v;
                else if (s < 8) Vout[(size_t)e * 576 + 256 + u * 5 + (s - 3)] = v;
                else g_h1[(size_t)e * 64 + u] = silu_c * v / (1.f + __expf(-v));
            }
}

// ---------------------------------------------------------------------------
// K3: MLP layers 2+3, envelope, xout, zero Vout scalar block
// ---------------------------------------------------------------------------
__global__ void __launch_bounds__(256) k3_mlp(const float* __restrict__ vectors,
                                              const float* __restrict__ W2,
                                              const float* __restrict__ W3,
                                              float* __restrict__ xout,
                                              float* __restrict__ Vout) {
    __shared__ float h1s[4][64], h2s[4][64];
    int tid = threadIdx.x, sub = tid >> 6, u = tid & 63;
    int e = blockIdx.x * 4 + sub;
    h1s[sub][u] = g_h1[(size_t)e * 64 + u];
    float silu_c = g_silu_c;
    __syncthreads();
    float acc = 0.f;
#pragma unroll 8
    for (int k = 0; k < 64; k++) acc += h1s[sub][k] * W2[k * 64 + u];
    float z = acc * 0.125f;
    h2s[sub][u] = silu_c * z / (1.f + __expf(-z));
    __syncthreads();
    acc = 0.f;
#pragma unroll 8
    for (int k = 0; k < 64; k++) acc += h2s[sub][k] * W3[k * 64 + u];
    float vx = vectors[3 * e], vy = vectors[3 * e + 1], vz = vectors[3 * e + 2];
    float d = sqrtf(vx * vx + vy * vy + vz * vz);
    float d3 = d * d * d, d6 = d3 * d3;
    float env = (d < 1.f) ? 1.f + d6 * (-28.f + d * (48.f - 21.f * d)) : 0.f;
    xout[(size_t)e * 64 + u] = env * acc * 0.125f;
    Vout[(size_t)e * 576 + u] = 0.f;
}

// ---------------------------------------------------------------------------
extern "C" void kernel_launch(void* const* d_in, const int* in_sizes, int n_in,
                              void* d_out, int out_size) {
    const float* vectors = (const float*)d_in[0];
    const float* x       = (const float*)d_in[1];
    const float* V       = (const float*)d_in[2];
    const int*   senders = (const int*)d_in[3];
    const float* W0      = (const float*)d_in[4];
    const float* W1      = (const float*)d_in[5];
    const float* W2      = (const float*)d_in[6];
    const float* W3      = (const float*)d_in[7];
    const float* Wl1     = (const float*)d_in[8];
    const float* Wl2     = (const float*)d_in[9];
    float* xout = (float*)d_out;
    float* Vout = xout + (size_t)NEDGES * 64;

    init_prep_kernel<<<2321, 256>>>(W0, W1, Wl1, Wl2);
    k1_scatter<<<2048, 256>>>(vectors, x, senders);
    k2a_tp<<<8192, 256>>>(V, senders);
    dim3 gg(256, 9);
    k_gemm<<<gg, 256>>>(Vout);
    k3_mlp<<<8192, 256>>>(vectors, W2, W3, xout, Vout);
}